// round 8
// baseline (speedup 1.0000x reference)
#include <cuda_runtime.h>
#include <math.h>

#define B_    256
#define V_    128000
#define H_    200
#define TOPK  50
#define TOPSZ 64

constexpr float TOPP = 0.9f;
constexpr float TEMP = 0.6f;
constexpr float PEN  = 1.2f;

// ---------- streaming config ----------
#define SPLIT  16
#define TILE   (V_ / SPLIT)      // 8000 elements per block
#define TW     (TILE / 32)       // 250 mask words
#define NT     512
#define CAP    1024
constexpr float T0 = 5.2f;       // conservative static candidate threshold (adjusted units)

// ---------- fallback (exact two-pass) config ----------
#define NBINS   2048
#define BSHIFT  21
#define BPC     (NBINS / NT)
#define CAPF    2048
#define MASKW   (V_ / 32)
#define IDXMASK 0x1FFFF

// ---------- device scratch (static globals: zero-initialized at load) ----------
__device__ int   g_cnt[B_];
__device__ int   g_done[B_];
__device__ float g_cval[B_][CAP];
__device__ int   g_cidx[B_][CAP];

__device__ __forceinline__ unsigned ordu(float f) {
    unsigned u = __float_as_uint(f);
    return (u & 0x80000000u) ? ~u : (u | 0x80000000u);
}

// ============ single fused kernel: stream + last-block-per-row finalize ============
__global__ __launch_bounds__(NT) void fused_kernel(
    const float* __restrict__ logits,
    const int*   __restrict__ prev,
    float*       __restrict__ out)
{
    // union workspace: stream phase uses sm_mask[0..TW); finalize fast path
    // aliases cv/ci/rk onto sm_mask; fallback uses everything. Phases are
    // sequential within a block, so aliasing is safe.
    __shared__ unsigned sm_mask[MASKW];   // 16000 B
    __shared__ int      sm_hist[NBINS];
    __shared__ float    sm_cval[CAPF];
    __shared__ int      sm_cidx[CAPF];
    __shared__ int      sm_chunk[NT];
    __shared__ float    sm_top[TOPSZ];
    __shared__ float    sm_e[TOPSZ];
    __shared__ int      sm_cnt;
    __shared__ int      sm_bstar;
    __shared__ int      sm_m, sm_nk;
    __shared__ int      s_last;
    __shared__ float    sm_v0, sm_invZ;

    const int blk  = blockIdx.x;
    const int row  = blk >> 4;        // SPLIT = 16
    const int tile = blk & 15;
    const int base = tile * TILE;
    const int tid  = threadIdx.x;

    // ---------------- streaming phase (this block's tile) ----------------
    if (tid < TW) sm_mask[tid] = 0u;
    __syncthreads();
    for (int i = tid; i < H_; i += NT) {
        int t = __ldg(&prev[row * H_ + i]) - base;
        if ((unsigned)t < (unsigned)TILE)
            atomicOr(&sm_mask[((unsigned)t) >> 5], 1u << (t & 31));
    }
    __syncthreads();

    {
        const float4* __restrict__ l4 = (const float4*)(logits + (size_t)row * V_ + base);
        float4* o4 = (float4*)(out + (size_t)row * V_ + base);
        const float4 z4 = make_float4(0.f, 0.f, 0.f, 0.f);

        #pragma unroll 8
        for (int i = tid; i < TILE / 4; i += NT) {
            float4 v = __ldcs(&l4[i]);
            int j = i << 2;
            unsigned mw = sm_mask[j >> 5];
            float a0 = v.x, a1 = v.y, a2 = v.z, a3 = v.w;
            if (mw != 0u) {                       // rare: ~12 of 8000 elements masked
                unsigned sh = j & 31;
                if ((mw >> (sh + 0)) & 1u) a0 = (a0 < 0.f) ? a0 * PEN : a0 / PEN;
                if ((mw >> (sh + 1)) & 1u) a1 = (a1 < 0.f) ? a1 * PEN : a1 / PEN;
                if ((mw >> (sh + 2)) & 1u) a2 = (a2 < 0.f) ? a2 * PEN : a2 / PEN;
                if ((mw >> (sh + 3)) & 1u) a3 = (a3 < 0.f) ? a3 * PEN : a3 / PEN;
            }
            a0 /= TEMP; a1 /= TEMP; a2 /= TEMP; a3 /= TEMP;
            __stcs(&o4[i], z4);
            if (a0 >= T0) { int p = atomicAdd(&g_cnt[row], 1); if (p < CAP) { g_cval[row][p] = a0; g_cidx[row][p] = base + j + 0; } }
            if (a1 >= T0) { int p = atomicAdd(&g_cnt[row], 1); if (p < CAP) { g_cval[row][p] = a1; g_cidx[row][p] = base + j + 1; } }
            if (a2 >= T0) { int p = atomicAdd(&g_cnt[row], 1); if (p < CAP) { g_cval[row][p] = a2; g_cidx[row][p] = base + j + 2; } }
            if (a3 >= T0) { int p = atomicAdd(&g_cnt[row], 1); if (p < CAP) { g_cval[row][p] = a3; g_cidx[row][p] = base + j + 3; } }
        }
    }
    __syncthreads();

    // ---------------- last-block-per-row election ----------------
    if (tid == 0) {
        __threadfence();                              // release candidate writes
        int d = atomicAdd(&g_done[row], 1);
        s_last = (d == SPLIT - 1);
    }
    __syncthreads();
    if (!s_last) return;
    __threadfence();                                  // acquire all tiles' writes
    if (tid == 0) g_done[row] = 0;                    // reset for next replay

    const int cnt = g_cnt[row];
    float* orow = out + (size_t)row * V_;

    if (cnt >= TOPK && cnt <= CAP) {
        // ---------- fast path ----------
        float* cv = (float*)sm_mask;                 // CAP floats
        int*   ci = (int*)(sm_mask + CAP);           // CAP ints
        short* rk = (short*)(sm_mask + 2 * CAP);     // CAP shorts
        const int n = cnt;

        for (int i = tid; i < n; i += NT) { cv[i] = g_cval[row][i]; ci[i] = g_cidx[row][i]; }
        __syncthreads();

        // counting-rank with vocab-index tiebreak (== stable argsort desc)
        for (int i = tid; i < n; i += NT) {
            float v = cv[i];
            int idx = ci[i];
            int r = 0;
            for (int k = 0; k < n; k++) {
                float w = cv[k];
                r += (w > v) || (w == v && ci[k] < idx);
            }
            if (r < TOPSZ) sm_top[r] = v;
            rk[i] = (short)(r < 32767 ? r : 32767);
        }
        __syncthreads();

        // top-k tie extension (JAX keeps all values == 50th-largest)
        if (tid == 0) {
            float v50 = sm_top[TOPK - 1];
            int lim = n < TOPSZ ? n : TOPSZ;
            int nk = TOPK;
            while (nk < lim && sm_top[nk] == v50) nk++;
            sm_nk = nk;
            g_cnt[row] = 0;                          // reset for next replay
        }
        __syncthreads();
        const int nk = sm_nk;
        if (tid < nk) sm_e[tid] = expf(sm_top[tid] - sm_top[0]);   // parallel expf
        __syncthreads();

        if (tid == 0) {
            float Z = 0.f;
            for (int i = 0; i < nk; i++) Z += sm_e[i];
            float cum = 0.f, S = 0.f;
            int m = 0;
            for (int i = 0; i < nk; i++) {
                if (i > 0 && cum > TOPP) break;      // HF shift-right semantics
                cum += sm_e[i] / Z;
                S   += sm_e[i];
                m = i + 1;
            }
            sm_v0 = sm_top[0]; sm_m = m; sm_invZ = 1.f / S;
        }
        __syncthreads();

        const float v0 = sm_v0, invZ = sm_invZ;
        const int m = sm_m;
        for (int i = tid; i < n; i += NT) {
            if (rk[i] < m) orow[ci[i]] = expf(cv[i] - v0) * invZ;
        }
        return;
    }

    // ---------- exact fallback: full two-pass over the row ----------
    const float4* __restrict__ l4 = (const float4*)(logits + (size_t)row * V_);
    const int NV4 = V_ / 4;

    for (int i = tid; i < MASKW; i += NT) sm_mask[i] = 0u;
    for (int i = tid; i < NBINS; i += NT) sm_hist[i] = 0;
    if (tid == 0) { sm_cnt = 0; g_cnt[row] = 0; }
    __syncthreads();
    for (int i = tid; i < H_; i += NT) {
        int t = prev[row * H_ + i];
        atomicOr(&sm_mask[((unsigned)t) >> 5], 1u << (t & 31));
    }
    __syncthreads();

    for (int i = tid; i < NV4; i += NT) {
        float4 v = l4[i];
        int j = i << 2;
        unsigned mw = sm_mask[j >> 5];
        unsigned sh = j & 31;
        float a;
        a = v.x; if ((mw >> (sh + 0)) & 1u) a = (a < 0.f) ? a * PEN : a / PEN; a /= TEMP;
        atomicAdd(&sm_hist[ordu(a) >> BSHIFT], 1);
        a = v.y; if ((mw >> (sh + 1)) & 1u) a = (a < 0.f) ? a * PEN : a / PEN; a /= TEMP;
        atomicAdd(&sm_hist[ordu(a) >> BSHIFT], 1);
        a = v.z; if ((mw >> (sh + 2)) & 1u) a = (a < 0.f) ? a * PEN : a / PEN; a /= TEMP;
        atomicAdd(&sm_hist[ordu(a) >> BSHIFT], 1);
        a = v.w; if ((mw >> (sh + 3)) & 1u) a = (a < 0.f) ? a * PEN : a / PEN; a /= TEMP;
        atomicAdd(&sm_hist[ordu(a) >> BSHIFT], 1);
    }
    __syncthreads();

    {
        int s = 0;
        #pragma unroll
        for (int k = 0; k < BPC; k++) s += sm_hist[tid * BPC + k];
        sm_chunk[tid] = s;
        __syncthreads();
        for (int off = 1; off < NT; off <<= 1) {
            int add = (tid + off < NT) ? sm_chunk[tid + off] : 0;
            __syncthreads();
            sm_chunk[tid] += add;
            __syncthreads();
        }
        int myv = sm_chunk[tid];
        int nxt = (tid + 1 < NT) ? sm_chunk[tid + 1] : 0;
        if (myv >= TOPK && nxt < TOPK) {
            int run = nxt;
            int bstar = tid * BPC;
            for (int b = tid * BPC + BPC - 1; b >= tid * BPC; b--) {
                run += sm_hist[b];
                if (run >= TOPK) { bstar = b; break; }
            }
            sm_bstar = bstar;
        }
    }
    __syncthreads();
    const unsigned uth = ((unsigned)sm_bstar) << BSHIFT;

    for (int i = tid; i < NV4; i += NT) {
        float4 v = l4[i];
        int j = i << 2;
        unsigned mw = sm_mask[j >> 5];
        unsigned sh = j & 31;
        float a0 = v.x; if ((mw >> (sh + 0)) & 1u) a0 = (a0 < 0.f) ? a0 * PEN : a0 / PEN; a0 /= TEMP;
        float a1 = v.y; if ((mw >> (sh + 1)) & 1u) a1 = (a1 < 0.f) ? a1 * PEN : a1 / PEN; a1 /= TEMP;
        float a2 = v.z; if ((mw >> (sh + 2)) & 1u) a2 = (a2 < 0.f) ? a2 * PEN : a2 / PEN; a2 /= TEMP;
        float a3 = v.w; if ((mw >> (sh + 3)) & 1u) a3 = (a3 < 0.f) ? a3 * PEN : a3 / PEN; a3 /= TEMP;
        if (ordu(a0) >= uth) { int p = atomicAdd(&sm_cnt, 1); if (p < CAPF) { sm_cval[p] = a0; sm_cidx[p] = j + 0; } }
        if (ordu(a1) >= uth) { int p = atomicAdd(&sm_cnt, 1); if (p < CAPF) { sm_cval[p] = a1; sm_cidx[p] = j + 1; } }
        if (ordu(a2) >= uth) { int p = atomicAdd(&sm_cnt, 1); if (p < CAPF) { sm_cval[p] = a2; sm_cidx[p] = j + 2; } }
        if (ordu(a3) >= uth) { int p = atomicAdd(&sm_cnt, 1); if (p < CAPF) { sm_cval[p] = a3; sm_cidx[p] = j + 3; } }
    }
    __syncthreads();
    const int n = sm_cnt < CAPF ? sm_cnt : CAPF;

    for (int i = tid; i < n; i += NT) {
        float v = sm_cval[i];
        int idx = sm_cidx[i] & IDXMASK;
        int r = 0;
        for (int k = 0; k < n; k++) {
            float w = sm_cval[k];
            r += (w > v) || (w == v && (sm_cidx[k] & IDXMASK) < idx);
        }
        if (r < TOPSZ) sm_top[r] = v;
        int rc = r < 255 ? r : 255;
        sm_cidx[i] = idx | (rc << 17);
    }
    __syncthreads();

    if (tid == 0) {
        float v50 = sm_top[TOPK - 1];
        int lim = n < TOPSZ ? n : TOPSZ;
        int nk = TOPK;
        while (nk < lim && sm_top[nk] == v50) nk++;
        float v0 = sm_top[0];
        float Z = 0.f;
        for (int i = 0; i < nk; i++) { sm_e[i] = expf(sm_top[i] - v0); Z += sm_e[i]; }
        float cum = 0.f, S = 0.f;
        int m = 0;
        for (int i = 0; i < nk; i++) {
            if (i > 0 && cum > TOPP) break;
            cum += sm_e[i] / Z;
            S   += sm_e[i];
            m = i + 1;
        }
        sm_v0 = v0; sm_m = m; sm_invZ = 1.f / S;
    }
    __syncthreads();

    {
        const float v0 = sm_v0, invZ = sm_invZ;
        const int m = sm_m;
        for (int i = tid; i < n; i += NT) {
            int packed = sm_cidx[i];
            int r = packed >> 17;
            if (r < m) orow[packed & IDXMASK] = expf(sm_cval[i] - v0) * invZ;
        }
    }
}

extern "C" void kernel_launch(void* const* d_in, const int* in_sizes, int n_in,
                              void* d_out, int out_size) {
    const float* logits = (const float*)d_in[0];
    const int*   prev   = (const int*)d_in[1];
    float*       out    = (float*)d_out;

    fused_kernel<<<B_ * SPLIT, NT>>>(logits, prev, out);
}

// round 9
// speedup vs baseline: 1.1847x; 1.1847x over previous
#include <cuda_runtime.h>
#include <math.h>

#define B_    256
#define V_    128000
#define H_    200
#define TOPK  50
#define TOPSZ 64

constexpr float TOPP = 0.9f;
constexpr float TEMP = 0.6f;
constexpr float PEN  = 1.2f;

// ---------- streaming config ----------
#define SPLIT  16
#define TILE   (V_ / SPLIT)      // 8000 elements per block
#define TW     (TILE / 32)       // 250 mask words
#define NT     512
#define CAP    1024
constexpr float T0 = 5.2f;       // conservative static candidate threshold (adjusted units)

// ---------- fallback (exact two-pass) config ----------
#define NBINS   2048
#define BSHIFT  21
#define BPC     (NBINS / NT)
#define CAPF    2048
#define MASKW   (V_ / 32)
#define IDXMASK 0x1FFFF

// ---------- device scratch (static globals: zero-initialized at load) ----------
__device__ int   g_cnt[B_];
__device__ float g_cval[B_][CAP];
__device__ int   g_cidx[B_][CAP];

__device__ __forceinline__ unsigned ordu(float f) {
    unsigned u = __float_as_uint(f);
    return (u & 0x80000000u) ? ~u : (u | 0x80000000u);
}

// ============ K1: fused stream: read logits, penalty+temp, zero-fill out, collect candidates ============
__global__ __launch_bounds__(NT) void pass1_kernel(
    const float* __restrict__ logits,
    const int*   __restrict__ prev,
    float*       __restrict__ out)
{
    __shared__ unsigned sm_mask[TW];

    const int blk  = blockIdx.x;
    const int row  = blk >> 4;        // SPLIT = 16
    const int tile = blk & 15;
    const int base = tile * TILE;
    const int tid  = threadIdx.x;

    if (tid < TW) sm_mask[tid] = 0u;
    __syncthreads();
    for (int i = tid; i < H_; i += NT) {
        int t = __ldg(&prev[row * H_ + i]) - base;
        if ((unsigned)t < (unsigned)TILE)
            atomicOr(&sm_mask[((unsigned)t) >> 5], 1u << (t & 31));
    }
    __syncthreads();

    const float4* __restrict__ l4 = (const float4*)(logits + (size_t)row * V_ + base);
    float4* o4 = (float4*)(out + (size_t)row * V_ + base);
    const float4 z4 = make_float4(0.f, 0.f, 0.f, 0.f);

    #pragma unroll 8
    for (int i = tid; i < TILE / 4; i += NT) {
        float4 v = __ldcs(&l4[i]);
        int j = i << 2;
        unsigned mw = sm_mask[j >> 5];
        float a0 = v.x, a1 = v.y, a2 = v.z, a3 = v.w;
        if (mw != 0u) {                       // rare: ~12 of 8000 elements masked
            unsigned sh = j & 31;
            if ((mw >> (sh + 0)) & 1u) a0 = (a0 < 0.f) ? a0 * PEN : a0 / PEN;
            if ((mw >> (sh + 1)) & 1u) a1 = (a1 < 0.f) ? a1 * PEN : a1 / PEN;
            if ((mw >> (sh + 2)) & 1u) a2 = (a2 < 0.f) ? a2 * PEN : a2 / PEN;
            if ((mw >> (sh + 3)) & 1u) a3 = (a3 < 0.f) ? a3 * PEN : a3 / PEN;
        }
        a0 /= TEMP; a1 /= TEMP; a2 /= TEMP; a3 /= TEMP;
        __stcs(&o4[i], z4);
        if (a0 >= T0) { int p = atomicAdd(&g_cnt[row], 1); if (p < CAP) { g_cval[row][p] = a0; g_cidx[row][p] = base + j + 0; } }
        if (a1 >= T0) { int p = atomicAdd(&g_cnt[row], 1); if (p < CAP) { g_cval[row][p] = a1; g_cidx[row][p] = base + j + 1; } }
        if (a2 >= T0) { int p = atomicAdd(&g_cnt[row], 1); if (p < CAP) { g_cval[row][p] = a2; g_cidx[row][p] = base + j + 2; } }
        if (a3 >= T0) { int p = atomicAdd(&g_cnt[row], 1); if (p < CAP) { g_cval[row][p] = a3; g_cidx[row][p] = base + j + 3; } }
    }
}

// ============ K2: per-row selection + nucleus + scatter; exact fallback inline;
//               self-resets g_cnt so the next graph replay starts clean ============
__global__ __launch_bounds__(NT) void finalize_kernel(
    const float* __restrict__ logits,
    const int*   __restrict__ prev,
    float*       __restrict__ out)
{
    // big arrays shared between fast path and fallback path (never concurrently)
    __shared__ unsigned sm_mask[MASKW];   // fallback mask; fast path reuses as cv/ci/rk
    __shared__ int      sm_hist[NBINS];
    __shared__ float    sm_cval[CAPF];
    __shared__ int      sm_cidx[CAPF];
    __shared__ int      sm_chunk[NT];
    __shared__ float    sm_top[TOPSZ];
    __shared__ float    sm_e[TOPSZ];
    __shared__ int      sm_cnt;
    __shared__ int      sm_bstar;
    __shared__ int      sm_m, sm_nk;
    __shared__ float    sm_v0, sm_invZ;

    const int row = blockIdx.x;
    const int tid = threadIdx.x;
    const int cnt = g_cnt[row];
    float* orow = out + (size_t)row * V_;

    if (cnt >= TOPK && cnt <= CAP) {
        // ---------- fast path ----------
        float* cv = (float*)sm_mask;                 // CAP floats (16B aligned)
        int*   ci = (int*)(sm_mask + CAP);           // CAP ints  (16B aligned)
        short* rk = (short*)(sm_mask + 2 * CAP);     // CAP shorts
        const int n = cnt;

        for (int i = tid; i < n; i += NT) { cv[i] = g_cval[row][i]; ci[i] = g_cidx[row][i]; }
        __syncthreads();

        // counting-rank with vocab-index tiebreak (== stable argsort desc),
        // inner loop vectorized 4x via LDS.128 broadcast
        const float4* cv4 = (const float4*)cv;
        const int4*   ci4 = (const int4*)ci;
        const int n4 = n >> 2;
        for (int i = tid; i < n; i += NT) {
            float v = cv[i];
            int idx = ci[i];
            int r = 0;
            for (int k4 = 0; k4 < n4; k4++) {
                float4 w = cv4[k4];
                int4   d = ci4[k4];
                r += (w.x > v) || (w.x == v && d.x < idx);
                r += (w.y > v) || (w.y == v && d.y < idx);
                r += (w.z > v) || (w.z == v && d.z < idx);
                r += (w.w > v) || (w.w == v && d.w < idx);
            }
            for (int k = n4 << 2; k < n; k++) {
                float w = cv[k];
                r += (w > v) || (w == v && ci[k] < idx);
            }
            if (r < TOPSZ) sm_top[r] = v;
            rk[i] = (short)(r < 32767 ? r : 32767);
        }
        __syncthreads();

        // top-k tie extension (JAX keeps all values == 50th-largest)
        if (tid == 0) {
            float v50 = sm_top[TOPK - 1];
            int lim = n < TOPSZ ? n : TOPSZ;
            int nk = TOPK;
            while (nk < lim && sm_top[nk] == v50) nk++;
            sm_nk = nk;
            g_cnt[row] = 0;                          // reset for next replay
        }
        __syncthreads();
        const int nk = sm_nk;
        if (tid < nk) sm_e[tid] = expf(sm_top[tid] - sm_top[0]);   // parallel expf
        __syncthreads();

        if (tid == 0) {
            float Z = 0.f;
            for (int i = 0; i < nk; i++) Z += sm_e[i];
            float cum = 0.f, S = 0.f;
            int m = 0;
            for (int i = 0; i < nk; i++) {
                if (i > 0 && cum > TOPP) break;      // HF shift-right semantics
                cum += sm_e[i] / Z;
                S   += sm_e[i];
                m = i + 1;
            }
            sm_m = m; sm_invZ = 1.f / S;
        }
        __syncthreads();

        const float invZ = sm_invZ;
        const int m = sm_m;
        for (int i = tid; i < n; i += NT) {
            int r = rk[i];
            if (r < m) orow[ci[i]] = sm_e[r] * invZ;   // reuse exp by rank (bitwise identical)
        }
        return;
    }

    // ---------- exact fallback: full two-pass over the row ----------
    const float4* __restrict__ l4 = (const float4*)(logits + (size_t)row * V_);
    const int NV4 = V_ / 4;

    for (int i = tid; i < MASKW; i += NT) sm_mask[i] = 0u;
    for (int i = tid; i < NBINS; i += NT) sm_hist[i] = 0;
    if (tid == 0) { sm_cnt = 0; g_cnt[row] = 0; }
    __syncthreads();
    for (int i = tid; i < H_; i += NT) {
        int t = prev[row * H_ + i];
        atomicOr(&sm_mask[((unsigned)t) >> 5], 1u << (t & 31));
    }
    __syncthreads();

    for (int i = tid; i < NV4; i += NT) {
        float4 v = l4[i];
        int j = i << 2;
        unsigned mw = sm_mask[j >> 5];
        unsigned sh = j & 31;
        float a;
        a = v.x; if ((mw >> (sh + 0)) & 1u) a = (a < 0.f) ? a * PEN : a / PEN; a /= TEMP;
        atomicAdd(&sm_hist[ordu(a) >> BSHIFT], 1);
        a = v.y; if ((mw >> (sh + 1)) & 1u) a = (a < 0.f) ? a * PEN : a / PEN; a /= TEMP;
        atomicAdd(&sm_hist[ordu(a) >> BSHIFT], 1);
        a = v.z; if ((mw >> (sh + 2)) & 1u) a = (a < 0.f) ? a * PEN : a / PEN; a /= TEMP;
        atomicAdd(&sm_hist[ordu(a) >> BSHIFT], 1);
        a = v.w; if ((mw >> (sh + 3)) & 1u) a = (a < 0.f) ? a * PEN : a / PEN; a /= TEMP;
        atomicAdd(&sm_hist[ordu(a) >> BSHIFT], 1);
    }
    __syncthreads();

    {
        int s = 0;
        #pragma unroll
        for (int k = 0; k < BPC; k++) s += sm_hist[tid * BPC + k];
        sm_chunk[tid] = s;
        __syncthreads();
        for (int off = 1; off < NT; off <<= 1) {
            int add = (tid + off < NT) ? sm_chunk[tid + off] : 0;
            __syncthreads();
            sm_chunk[tid] += add;
            __syncthreads();
        }
        int myv = sm_chunk[tid];
        int nxt = (tid + 1 < NT) ? sm_chunk[tid + 1] : 0;
        if (myv >= TOPK && nxt < TOPK) {
            int run = nxt;
            int bstar = tid * BPC;
            for (int b = tid * BPC + BPC - 1; b >= tid * BPC; b--) {
                run += sm_hist[b];
                if (run >= TOPK) { bstar = b; break; }
            }
            sm_bstar = bstar;
        }
    }
    __syncthreads();
    const unsigned uth = ((unsigned)sm_bstar) << BSHIFT;

    for (int i = tid; i < NV4; i += NT) {
        float4 v = l4[i];
        int j = i << 2;
        unsigned mw = sm_mask[j >> 5];
        unsigned sh = j & 31;
        float a0 = v.x; if ((mw >> (sh + 0)) & 1u) a0 = (a0 < 0.f) ? a0 * PEN : a0 / PEN; a0 /= TEMP;
        float a1 = v.y; if ((mw >> (sh + 1)) & 1u) a1 = (a1 < 0.f) ? a1 * PEN : a1 / PEN; a1 /= TEMP;
        float a2 = v.z; if ((mw >> (sh + 2)) & 1u) a2 = (a2 < 0.f) ? a2 * PEN : a2 / PEN; a2 /= TEMP;
        float a3 = v.w; if ((mw >> (sh + 3)) & 1u) a3 = (a3 < 0.f) ? a3 * PEN : a3 / PEN; a3 /= TEMP;
        if (ordu(a0) >= uth) { int p = atomicAdd(&sm_cnt, 1); if (p < CAPF) { sm_cval[p] = a0; sm_cidx[p] = j + 0; } }
        if (ordu(a1) >= uth) { int p = atomicAdd(&sm_cnt, 1); if (p < CAPF) { sm_cval[p] = a1; sm_cidx[p] = j + 1; } }
        if (ordu(a2) >= uth) { int p = atomicAdd(&sm_cnt, 1); if (p < CAPF) { sm_cval[p] = a2; sm_cidx[p] = j + 2; } }
        if (ordu(a3) >= uth) { int p = atomicAdd(&sm_cnt, 1); if (p < CAPF) { sm_cval[p] = a3; sm_cidx[p] = j + 3; } }
    }
    __syncthreads();
    const int n = sm_cnt < CAPF ? sm_cnt : CAPF;

    for (int i = tid; i < n; i += NT) {
        float v = sm_cval[i];
        int idx = sm_cidx[i] & IDXMASK;
        int r = 0;
        for (int k = 0; k < n; k++) {
            float w = sm_cval[k];
            r += (w > v) || (w == v && (sm_cidx[k] & IDXMASK) < idx);
        }
        if (r < TOPSZ) sm_top[r] = v;
        int rc = r < 255 ? r : 255;
        sm_cidx[i] = idx | (rc << 17);
    }
    __syncthreads();

    if (tid == 0) {
        float v50 = sm_top[TOPK - 1];
        int lim = n < TOPSZ ? n : TOPSZ;
        int nk = TOPK;
        while (nk < lim && sm_top[nk] == v50) nk++;
        float v0 = sm_top[0];
        float Z = 0.f;
        for (int i = 0; i < nk; i++) { sm_e[i] = expf(sm_top[i] - v0); Z += sm_e[i]; }
        float cum = 0.f, S = 0.f;
        int m = 0;
        for (int i = 0; i < nk; i++) {
            if (i > 0 && cum > TOPP) break;
            cum += sm_e[i] / Z;
            S   += sm_e[i];
            m = i + 1;
        }
        sm_v0 = v0; sm_m = m; sm_invZ = 1.f / S;
    }
    __syncthreads();

    {
        const float v0 = sm_v0, invZ = sm_invZ;
        const int m = sm_m;
        for (int i = tid; i < n; i += NT) {
            int packed = sm_cidx[i];
            int r = packed >> 17;
            if (r < m) orow[packed & IDXMASK] = expf(sm_cval[i] - v0) * invZ;
        }
    }
}

extern "C" void kernel_launch(void* const* d_in, const int* in_sizes, int n_in,
                              void* d_out, int out_size) {
    const float* logits = (const float*)d_in[0];
    const int*   prev   = (const int*)d_in[1];
    float*       out    = (float*)d_out;

    pass1_kernel<<<B_ * SPLIT, NT>>>(logits, prev, out);
    finalize_kernel<<<B_, NT>>>(logits, prev, out);
}